// round 11
// baseline (speedup 1.0000x reference)
#include <cuda_runtime.h>
#include <math.h>
#include <stdint.h>

// ---------------------------------------------------------------------------
// Problem constants
// ---------------------------------------------------------------------------
#define B_   8
#define C_   128
#define N_   4096
#define EPSN 1e-12f
// exp(x/0.1) = 2^(x * 10*log2(e)); fold sqrt of scale into both vectors.
#define ALPHA 3.7982826f          // sqrt(14.4269504089)

#define TM   128                  // rows per unit
#define TN   128                  // cols per iteration tile
#define IPU  8                    // iterations (col tiles) per unit
#define NU   (B_ * 32 * 4)        // 1024 work units
#define GRIDP 148                 // persistent CTAs

// Scratch: normalized+scaled features e4m3, [b][n][c] (4 MB)
__device__ __align__(16) uint8_t g_v8[(size_t)B_ * N_ * C_];
// Per-row partial sums (merged across col-quarter units)
__device__ float g_pos[B_ * N_];
__device__ float g_tot[B_ * N_];

// ---------------------------------------------------------------------------
// Helpers
// ---------------------------------------------------------------------------
__device__ __forceinline__ uint32_t smem_u32(const void* p) {
    uint32_t a;
    asm("{ .reg .u64 t; cvta.to.shared.u64 t, %1; cvt.u32.u64 %0, t; }"
        : "=r"(a) : "l"(p));
    return a;
}

__device__ __forceinline__ float ex2f(float x) {
    float y;
    asm("ex2.approx.f32 %0, %1;" : "=f"(y) : "f"(x));
    return y;
}

#define LDSM4(R0, R1, R2, R3, ADDR) \
    asm volatile("ldmatrix.sync.aligned.m8n8.x4.shared.b16 {%0,%1,%2,%3}, [%4];" \
                 : "=r"(R0), "=r"(R1), "=r"(R2), "=r"(R3) : "r"(ADDR))

// fp8 e4m3 MMA, m16n8k32, fp32 accumulate
#define MMAF8(AC, A0, A1, A2, A3, Bv0, Bv1) \
    asm volatile("mma.sync.aligned.m16n8k32.row.col.f32.e4m3.e4m3.f32 " \
                 "{%0,%1,%2,%3}, {%4,%5,%6,%7}, {%8,%9}, {%0,%1,%2,%3};" \
                 : "+f"((AC)[0]), "+f"((AC)[1]), "+f"((AC)[2]), "+f"((AC)[3]) \
                 : "r"(A0), "r"(A1), "r"(A2), "r"(A3), "r"(Bv0), "r"(Bv1))

#define CP_ASYNC16(DST, SRC) \
    asm volatile("cp.async.cg.shared.global [%0], [%1], 16;" :: "r"(DST), "l"(SRC))
#define CP_COMMIT()  asm volatile("cp.async.commit_group;" ::: "memory")
#define CP_WAIT0()   asm volatile("cp.async.wait_group 0;" ::: "memory")

// ---------------------------------------------------------------------------
// Kernel 1: normalize + scale by ALPHA + transpose -> e4m3 [b][n][c].
// Also zeroes g_pos/g_tot rows and the output scalar (folded zero_kernel).
// ---------------------------------------------------------------------------
__global__ void normalize_kernel(const float* __restrict__ feat,
                                 float* __restrict__ out) {
    __shared__ float t[C_][33];
    __shared__ float invn[32];
    const int b = blockIdx.y, n0 = blockIdx.x * 32, tid = threadIdx.x;
    const float* fb = feat + (size_t)b * C_ * N_;

    if (tid < 32) {
        g_pos[b * N_ + n0 + tid] = 0.0f;
        g_tot[b * N_ + n0 + tid] = 0.0f;
    }
    if (b == 0 && n0 == 0 && tid == 32) out[0] = 0.0f;

    for (int idx = tid; idx < C_ * 32; idx += 256) {
        int c = idx >> 5, nl = idx & 31;
        t[c][nl] = fb[(size_t)c * N_ + n0 + nl];
    }
    __syncthreads();

    const int w = tid >> 5, lane = tid & 31;
    #pragma unroll
    for (int p = 0; p < 4; p++) {
        int nl = w * 4 + p;
        float v0 = t[lane][nl], v1 = t[lane + 32][nl];
        float v2 = t[lane + 64][nl], v3 = t[lane + 96][nl];
        float s = v0 * v0 + v1 * v1 + v2 * v2 + v3 * v3;
        #pragma unroll
        for (int o = 16; o > 0; o >>= 1) s += __shfl_xor_sync(0xffffffffu, s, o);
        if (lane == 0) invn[nl] = ALPHA / fmaxf(sqrtf(s), EPSN);
    }
    __syncthreads();

    // write e4m3 pairs: vb16[nl*64 + cp] = {v[2cp+1], v[2cp]}
    unsigned short* vb = (unsigned short*)(g_v8 + ((size_t)b * N_ + n0) * C_);
    for (int idx = tid; idx < 32 * 64; idx += 256) {
        int nl = idx >> 6, cp = idx & 63;
        float s = invn[nl];
        float f0 = t[cp * 2][nl] * s;
        float f1 = t[cp * 2 + 1][nl] * s;
        unsigned short u;
        asm("cvt.rn.satfinite.e4m3x2.f32 %0, %1, %2;"
            : "=h"(u) : "f"(f1), "f"(f0));
        vb[nl * 64 + cp] = u;
    }
}

// ---------------------------------------------------------------------------
// Tile copy: 128 rows x 128B (fp8) global -> swizzled smem via cp.async.
// Swizzle: physical 16B-chunk = c ^ (row & 7)
// ---------------------------------------------------------------------------
__device__ __forceinline__ void cp_tile8(uint32_t sbase,
                                         const uint8_t* __restrict__ src,
                                         int tid) {
    #pragma unroll
    for (int it = 0; it < 4; it++) {
        int idx = tid + it * 256;
        int r = idx >> 3, c = idx & 7;
        uint32_t dst = sbase + (uint32_t)r * 128u + (uint32_t)((c ^ (r & 7)) << 4);
        const char* g = (const char*)src + (size_t)r * 128 + c * 16;
        CP_ASYNC16(dst, g);
    }
}

// ---------------------------------------------------------------------------
// Half-tile K-loop (fp8): 32 rows x 32 cols x K=128 -> acc[2][4][4].
// 4 k-steps of 32; per step 2 ldmatrix.x4 + 8 MMAs.
// ---------------------------------------------------------------------------
__device__ __forceinline__ void khalf8(float (&acc)[2][4][4],
                                       const uint32_t (&af)[2][4][4],
                                       uint32_t sB,
                                       uint32_t bRow0, int bR70,
                                       uint32_t bRow1, int bR71, int csB) {
    #pragma unroll
    for (int mt = 0; mt < 2; mt++)
        #pragma unroll
        for (int nt = 0; nt < 4; nt++)
            #pragma unroll
            for (int q = 0; q < 4; q++) acc[mt][nt][q] = 0.0f;

    #pragma unroll
    for (int ks = 0; ks < 4; ks++) {
        uint32_t bf0[4], bf1[4];
        LDSM4(bf0[0], bf0[1], bf0[2], bf0[3],
              sB + bRow0 + (uint32_t)(((2 * ks + csB) ^ bR70) << 4));
        LDSM4(bf1[0], bf1[1], bf1[2], bf1[3],
              sB + bRow1 + (uint32_t)(((2 * ks + csB) ^ bR71) << 4));
        #pragma unroll
        for (int mt = 0; mt < 2; mt++) {
            MMAF8(acc[mt][0], af[mt][ks][0], af[mt][ks][1], af[mt][ks][2],
                  af[mt][ks][3], bf0[0], bf0[1]);
            MMAF8(acc[mt][1], af[mt][ks][0], af[mt][ks][1], af[mt][ks][2],
                  af[mt][ks][3], bf0[2], bf0[3]);
            MMAF8(acc[mt][2], af[mt][ks][0], af[mt][ks][1], af[mt][ks][2],
                  af[mt][ks][3], bf1[0], bf1[1]);
            MMAF8(acc[mt][3], af[mt][ks][0], af[mt][ks][1], af[mt][ks][2],
                  af[mt][ks][3], bf1[2], bf1[3]);
        }
    }
}

// ---------------------------------------------------------------------------
// Epilogue of one half-tile: exp2, diagonal removal, label masking.
// ---------------------------------------------------------------------------
__device__ __forceinline__ void epi_half(const float (&acc)[2][4][4],
                                         int i, int h,
                                         const unsigned* __restrict__ cmask,
                                         const int (&labr)[2][2],
                                         const int (&growb)[2],
                                         int warpN, int lane, int rt, int cq,
                                         float (&pos)[4], float (&tot)[4]) {
    const int coff = warpN + h * 32;
    const int lw = i * 4 + (coff >> 5);
    const int cb = cq * 1024 + i * 128 + coff;
    const bool diagHere = (rt == cq * 8 + i);
    #pragma unroll
    for (int mt = 0; mt < 2; mt++) {
        const unsigned w0 = cmask[labr[mt][0] * 32 + lw];
        const unsigned w1 = cmask[labr[mt][1] * 32 + lw];
        const int g0 = growb[mt], g1 = growb[mt] + 8;
        float t0 = 0.f, t1 = 0.f, p0 = 0.f, p1 = 0.f;
        #pragma unroll
        for (int ntl = 0; ntl < 4; ntl++) {
            const int sh = ntl * 8 + 2 * (lane & 3);
            const unsigned b0 = w0 >> sh;
            const unsigned b1 = w1 >> sh;
            float e00 = ex2f(acc[mt][ntl][0]);
            float e01 = ex2f(acc[mt][ntl][1]);
            float e10 = ex2f(acc[mt][ntl][2]);
            float e11 = ex2f(acc[mt][ntl][3]);
            if (diagHere) {
                const int gc = cb + ntl * 8 + 2 * (lane & 3);
                if (g0 == gc)     e00 = 0.f;
                if (g0 == gc + 1) e01 = 0.f;
                if (g1 == gc)     e10 = 0.f;
                if (g1 == gc + 1) e11 = 0.f;
            }
            t0 += e00 + e01;
            t1 += e10 + e11;
            p0 += ((b0 & 1u) ? e00 : 0.f) + ((b0 & 2u) ? e01 : 0.f);
            p1 += ((b1 & 1u) ? e10 : 0.f) + ((b1 & 2u) ? e11 : 0.f);
        }
        tot[mt * 2 + 0] += t0;  tot[mt * 2 + 1] += t1;
        pos[mt * 2 + 0] += p0;  pos[mt * 2 + 1] += p1;
    }
}

// ---------------------------------------------------------------------------
// Kernel 2: persistent FP8 MMA GEMM + pipelined exp2/mask epilogue.
// Unit u: b = u>>7, rt = (u>>2)&31, cq = u&3. 128 rows x 1024 cols per unit.
// Dyn smem: A 16K | B0 16K | B1 16K | cmask 2K | posS 1K | totS 1K = 52K
// ---------------------------------------------------------------------------
#define SM_B0    16384
#define SM_B1    32768
#define SM_CMASK 49152
#define SM_POSS  (SM_CMASK + 2048)
#define SM_TOTS  (SM_POSS + 1024)
#define SM_DYN   (SM_TOTS + 1024)

__global__ void __launch_bounds__(256, 1)
loss_kernel(const int* __restrict__ labels) {
    extern __shared__ char sm[];
    const int tid = threadIdx.x, wid = tid >> 5, lane = tid & 31;

    unsigned* cmask = (unsigned*)(sm + SM_CMASK);   // [16 classes][32 words]
    float* posS = (float*)(sm + SM_POSS);           // [128][2]
    float* totS = (float*)(sm + SM_TOTS);

    const uint32_t sA  = smem_u32(sm);
    const uint32_t sB0 = smem_u32(sm + SM_B0);
    const uint32_t sB1 = smem_u32(sm + SM_B1);

    const int warpM = (wid & 3) * 32;
    const int warpN = (wid >> 2) * 64;

    // ldmatrix per-lane address components (16B-chunk granularity)
    const int rA  = warpM + (lane & 15);
    const int csA = lane >> 4;
    const int rBl = (lane & 7) + ((lane & 16) >> 1);
    const int csB = (lane >> 3) & 1;

    uint32_t bRow[4];
    int bR7[4];
    #pragma unroll
    for (int np = 0; np < 4; np++) {
        int row = warpN + np * 16 + rBl;
        bRow[np] = (uint32_t)row * 128u;
        bR7[np] = row & 7;
    }

    int u = blockIdx.x;
    if (u < NU) {   // prologue loads for first unit
        const int b = u >> 7, rt = (u >> 2) & 31, cq = u & 3;
        const uint8_t* vb = g_v8 + (size_t)b * N_ * C_;
        cp_tile8(sA,  vb + (size_t)(rt * TM) * C_, tid);
        cp_tile8(sB0, vb + (size_t)(cq * 1024) * C_, tid);
        CP_COMMIT();
    }

    while (u < NU) {
        const int b = u >> 7, rt = (u >> 2) & 31, cq = u & 3;
        const int un = u + gridDim.x;
        const int* lb = labels + b * N_;
        const uint8_t* vb = g_v8 + (size_t)b * N_ * C_;

        CP_WAIT0();
        __syncthreads();    // A + B0 ready; prev unit fully done

        // per-class column bitmasks for this quarter (32 words per class)
        {
            int labv[4];
            #pragma unroll
            for (int i = 0; i < 4; i++)
                labv[i] = lb[cq * 1024 + (wid * 4 + i) * 32 + lane];
            #pragma unroll
            for (int i = 0; i < 4; i++)
                #pragma unroll
                for (int c = 0; c < 16; c++) {
                    unsigned m = __ballot_sync(0xffffffffu, labv[i] == c);
                    if (lane == c) cmask[c * 32 + wid * 4 + i] = m;
                }
        }

        // this thread's accumulator-row identities (in-batch rows)
        int growb[2], labr[2][2];
        #pragma unroll
        for (int mt = 0; mt < 2; mt++) {
            growb[mt] = rt * TM + warpM + mt * 16 + (lane >> 2);
            labr[mt][0] = lb[growb[mt]];
            labr[mt][1] = lb[growb[mt] + 8];
        }

        // A fragments cached in registers for the whole unit (32 regs)
        uint32_t af[2][4][4];
        #pragma unroll
        for (int mt = 0; mt < 2; mt++) {
            int row = rA + mt * 16;
            uint32_t base = sA + (uint32_t)row * 128u;
            int r7 = row & 7;
            #pragma unroll
            for (int ks = 0; ks < 4; ks++) {
                uint32_t addr = base + (uint32_t)(((2 * ks + csA) ^ r7) << 4);
                LDSM4(af[mt][ks][0], af[mt][ks][1], af[mt][ks][2],
                      af[mt][ks][3], addr);
            }
        }
        __syncthreads();    // cmask visible everywhere

        float pos[4] = {0.f, 0.f, 0.f, 0.f};
        float tot[4] = {0.f, 0.f, 0.f, 0.f};
        float acc0[2][4][4], acc1[2][4][4];

        for (int i = 0; i < IPU; i++) {
            const uint32_t sB = (i & 1) ? sB1 : sB0;
            if (i < IPU - 1) {
                cp_tile8(((i + 1) & 1) ? sB1 : sB0,
                         vb + (size_t)(cq * 1024 + (i + 1) * TN) * C_, tid);
                CP_COMMIT();
            } else if (un < NU) {
                const int bn = un >> 7, rtn = (un >> 2) & 31, cqn = un & 3;
                const uint8_t* vbn = g_v8 + (size_t)bn * N_ * C_;
                cp_tile8(sA,  vbn + (size_t)(rtn * TM) * C_, tid);
                cp_tile8(sB0, vbn + (size_t)(cqn * 1024) * C_, tid);
                CP_COMMIT();
            }

            // pipelined: K0(i), E1(i-1), K1(i), E0(i)
            khalf8(acc0, af, sB, bRow[0], bR7[0], bRow[1], bR7[1], csB);
            if (i > 0)
                epi_half(acc1, i - 1, 1, cmask, labr, growb, warpN, lane,
                         rt, cq, pos, tot);
            khalf8(acc1, af, sB, bRow[2], bR7[2], bRow[3], bR7[3], csB);
            epi_half(acc0, i, 0, cmask, labr, growb, warpN, lane,
                     rt, cq, pos, tot);

            CP_WAIT0();
            __syncthreads();
        }
        epi_half(acc1, IPU - 1, 1, cmask, labr, growb, warpN, lane,
                 rt, cq, pos, tot);

        // reduce 4 lanes per row, merge 2 N-warps, atomic to global
        #pragma unroll
        for (int q = 0; q < 4; q++) {
            pos[q] += __shfl_xor_sync(0xffffffffu, pos[q], 1);
            pos[q] += __shfl_xor_sync(0xffffffffu, pos[q], 2);
            tot[q] += __shfl_xor_sync(0xffffffffu, tot[q], 1);
            tot[q] += __shfl_xor_sync(0xffffffffu, tot[q], 2);
        }
        const int widN = wid >> 2;
        if ((lane & 3) == 0) {
            #pragma unroll
            for (int mt = 0; mt < 2; mt++) {
                int rl = warpM + mt * 16 + (lane >> 2);
                posS[rl * 2 + widN]       = pos[mt * 2 + 0];
                totS[rl * 2 + widN]       = tot[mt * 2 + 0];
                posS[(rl + 8) * 2 + widN] = pos[mt * 2 + 1];
                totS[(rl + 8) * 2 + widN] = tot[mt * 2 + 1];
            }
        }
        __syncthreads();
        if (tid < TM) {
            float P = posS[tid * 2] + posS[tid * 2 + 1];
            float T = totS[tid * 2] + totS[tid * 2 + 1];
            int gr = b * N_ + rt * TM + tid;
            atomicAdd(&g_pos[gr], P);
            atomicAdd(&g_tot[gr], T);
        }
        u = un;
    }
}

// ---------------------------------------------------------------------------
// Kernel 3: finalize — dev = log(T) - log(P) per row, mean into out.
// ---------------------------------------------------------------------------
__global__ void finalize_kernel(float* __restrict__ out) {
    __shared__ float ws[8];
    const int idx = blockIdx.x * 256 + threadIdx.x;
    const int lane = threadIdx.x & 31, wid = threadIdx.x >> 5;
    float dev = __logf(g_tot[idx]) - __logf(g_pos[idx]);
    #pragma unroll
    for (int o = 16; o > 0; o >>= 1) dev += __shfl_xor_sync(0xffffffffu, dev, o);
    if (lane == 0) ws[wid] = dev;
    __syncthreads();
    if (threadIdx.x == 0) {
        float s = 0.0f;
        #pragma unroll
        for (int w = 0; w < 8; w++) s += ws[w];
        atomicAdd(out, s * (1.0f / ((float)B_ * (float)N_)));
    }
}

// ---------------------------------------------------------------------------
// Launch
// ---------------------------------------------------------------------------
extern "C" void kernel_launch(void* const* d_in, const int* in_sizes, int n_in,
                              void* d_out, int out_size) {
    const float* feat   = (const float*)d_in[0];
    const int*   labels = (const int*)d_in[1];
    float*       out    = (float*)d_out;

    dim3 gn(N_ / 32, B_);
    normalize_kernel<<<gn, 256>>>(feat, out);

    cudaFuncSetAttribute(loss_kernel,
                         cudaFuncAttributeMaxDynamicSharedMemorySize, SM_DYN);
    loss_kernel<<<GRIDP, 256, SM_DYN>>>(labels);

    finalize_kernel<<<(B_ * N_) / 256, 256>>>(out);
}